// round 14
// baseline (speedup 1.0000x reference)
#include <cuda_runtime.h>
#include <cuda_bf16.h>
#include <cstdint>

#define Bq 8
#define Tq 512
#define Cq 1024
#define Hq 16
#define Eq 64
#define Lq 2048
#define Sq 2560   // L + T

// ---------------- split-bf16 scratch (device globals) ----------------
__device__ __align__(16) __nv_bfloat16 g_xh[4096*1024], g_xl[4096*1024];
__device__ __align__(16) __nv_bfloat16 g_wqh[3072*1024], g_wql[3072*1024];  // Wqkv^T (n,k)
__device__ __align__(16) __nv_bfloat16 g_wph[1024*1024], g_wpl[1024*1024];  // Wproj^T
__device__ __align__(16) __nv_bfloat16 g_qh[Bq*Hq*Tq*Eq], g_ql[Bq*Hq*Tq*Eq];
__device__ __align__(16) __nv_bfloat16 g_kh[Bq*Hq*Sq*Eq], g_kl[Bq*Hq*Sq*Eq];
__device__ __align__(16) __nv_bfloat16 g_vh[Bq*Hq*Sq*Eq], g_vl[Bq*Hq*Sq*Eq];
__device__ __align__(16) __nv_bfloat16 g_yh[4096*1024], g_yl[4096*1024];

// ---------------- PTX helpers ----------------
__device__ __forceinline__ void mma_bf16(float* c, const unsigned* a, const unsigned* b){
    asm volatile(
        "mma.sync.aligned.m16n8k16.row.col.f32.bf16.bf16.f32 "
        "{%0,%1,%2,%3}, {%4,%5,%6,%7}, {%8,%9}, {%0,%1,%2,%3};\n"
        : "+f"(c[0]), "+f"(c[1]), "+f"(c[2]), "+f"(c[3])
        : "r"(a[0]), "r"(a[1]), "r"(a[2]), "r"(a[3]), "r"(b[0]), "r"(b[1]));
}
__device__ __forceinline__ void ldsm4(unsigned* r, unsigned addr){
    asm volatile("ldmatrix.sync.aligned.m8n8.x4.shared.b16 {%0,%1,%2,%3}, [%4];\n"
                 : "=r"(r[0]), "=r"(r[1]), "=r"(r[2]), "=r"(r[3]) : "r"(addr));
}
__device__ __forceinline__ void ldsm2(unsigned* r, unsigned addr){
    asm volatile("ldmatrix.sync.aligned.m8n8.x2.shared.b16 {%0,%1}, [%2];\n"
                 : "=r"(r[0]), "=r"(r[1]) : "r"(addr));
}
__device__ __forceinline__ void ldsm2t(unsigned* r, unsigned addr){
    asm volatile("ldmatrix.sync.aligned.m8n8.x2.trans.shared.b16 {%0,%1}, [%2];\n"
                 : "=r"(r[0]), "=r"(r[1]) : "r"(addr));
}
__device__ __forceinline__ void cp16(uint32_t dst, const void* src){
    asm volatile("cp.async.cg.shared.global [%0], [%1], 16;" :: "r"(dst), "l"(src) : "memory");
}
#define CP_COMMIT() asm volatile("cp.async.commit_group;" ::: "memory")
#define CP_WAIT0()  asm volatile("cp.async.wait_group 0;" ::: "memory")

__device__ __forceinline__ float ex2(float x){
    float y; asm("ex2.approx.ftz.f32 %0, %1;" : "=f"(y) : "f"(x)); return y;
}

__device__ __forceinline__ void split_pack(float x, float y, unsigned& hi, unsigned& lo){
    __nv_bfloat16 hx = __float2bfloat16(x);
    __nv_bfloat16 hy = __float2bfloat16(y);
    __nv_bfloat16 lx = __float2bfloat16(x - __bfloat162float(hx));
    __nv_bfloat16 ly = __float2bfloat16(y - __bfloat162float(hy));
    __nv_bfloat162 H; H.x = hx; H.y = hy;
    __nv_bfloat162 Lo; Lo.x = lx; Lo.y = ly;
    hi = *reinterpret_cast<unsigned*>(&H);
    lo = *reinterpret_cast<unsigned*>(&Lo);
}
__device__ __forceinline__ void split_store(__nv_bfloat16* dh, __nv_bfloat16* dl,
                                            int idx, float x, float y){
    unsigned hi, lo; split_pack(x, y, hi, lo);
    *reinterpret_cast<unsigned*>(&dh[idx]) = hi;
    *reinterpret_cast<unsigned*>(&dl[idx]) = lo;
}

// ---------------- conversion bodies ----------------
__device__ __forceinline__ void wT_tile_body(const float* __restrict__ W, int N,
                                             __nv_bfloat16* oh, __nv_bfloat16* ol,
                                             int n0, int k0, float* tile /*32x33*/){
    int tx = threadIdx.x & 31, ty = threadIdx.x >> 5;
#pragma unroll
    for (int i = 0; i < 4; i++)
        tile[(ty + 8*i)*33 + tx] = W[(size_t)(k0 + ty + 8*i)*N + n0 + tx];
    __syncthreads();
#pragma unroll
    for (int i = 0; i < 4; i++){
        int n = n0 + ty + 8*i, k = k0 + tx;
        float v = tile[tx*33 + ty + 8*i];
        __nv_bfloat16 h = __float2bfloat16(v);
        oh[(size_t)n*1024 + k] = h;
        ol[(size_t)n*1024 + k] = __float2bfloat16(v - __bfloat162float(h));
    }
    __syncthreads();
}

// Pre-kernel: x split + Wqkv^T split (all predecessors of the QKV GEMM)
__global__ __launch_bounds__(256) void cvt_pre(const float* __restrict__ x,
                                               const float* __restrict__ Wqkv){
    __shared__ float tile[32*33];
    int bid = blockIdx.x;
    if (bid < 4096){
        int base = (bid*256 + threadIdx.x)*4;
        float4 v = *(const float4*)&x[base];
        split_store(g_xh, g_xl, base,   v.x, v.y);
        split_store(g_xh, g_xl, base+2, v.z, v.w);
    } else {
        int id = bid - 4096;                    // 0..3071
        int n0 = (id % 96)*32, k0 = (id / 96)*32;
        wT_tile_body(Wqkv, 3072, g_wqh, g_wql, n0, k0, tile);
    }
}

// ---------------- GEMM sizes ----------------
#define G_ARR  (128*40)
#define G_STG  (4*G_ARR)
#define GEMM_SMEM (2*G_STG*2)               // 81920 B

// log2(e)/8 : folds softmax base-2 conversion into the q scale
#define QSCALE 0.1803368801111204f

// Shared GEMM mainloop + epilogue (MODE 0 = qkv scatter, 1 = f32 out)
// MMA issue order is term-major over j-pairs: dependent-MMA reuse distance 4.
template<int MODE>
__device__ __forceinline__ void gemm_body(int bm, int bn,
                                          const float* __restrict__ bias,
                                          float* __restrict__ out,
                                          __nv_bfloat16* dsm){
    const __nv_bfloat16* Ah = MODE ? g_yh : g_xh;
    const __nv_bfloat16* Al = MODE ? g_yl : g_xl;
    const __nv_bfloat16* Bh = MODE ? g_wph : g_wqh;
    const __nv_bfloat16* Bl = MODE ? g_wpl : g_wql;

    const int t = threadIdx.x, L = t & 31, warp = t >> 5;
    const int wm = warp & 3, wn = warp >> 2;

    float c[2][8][4];
#pragma unroll
    for (int i=0;i<2;i++)
#pragma unroll
        for (int j=0;j<8;j++)
#pragma unroll
            for (int q=0;q<4;q++) c[i][j][q] = 0.f;

    const int lr = t >> 2, lc = t & 3;
    uint32_t sbase = (uint32_t)__cvta_generic_to_shared(dsm);
    uint32_t stg_b[2] = { sbase, sbase + G_STG*2 };

    const int arow = wm*32 + (L & 15);
    const int acol = (L >> 4)*8;
    const int brow = L & 7;
    const int bcol = ((L >> 3) & 1)*8;

    auto load_slab = [&](int k0, int stg){
        uint32_t sb = stg_b[stg];
#pragma unroll
        for (int hh = 0; hh < 2; hh++){
            int r = lr + hh*64;
            uint32_t d = sb + (uint32_t)((r*40 + lc*8)*2);
            size_t ga = (size_t)(bm + r)*1024 + k0 + lc*8;
            size_t gb = (size_t)(bn + r)*1024 + k0 + lc*8;
            cp16(d,                &Ah[ga]);
            cp16(d + G_ARR*2,      &Al[ga]);
            cp16(d + 2*G_ARR*2,    &Bh[gb]);
            cp16(d + 3*G_ARR*2,    &Bl[gb]);
        }
        CP_COMMIT();
    };

    load_slab(0, 0);

    for (int s = 0; s < 32; s++){
        CP_WAIT0();
        __syncthreads();
        if (s + 1 < 32) load_slab((s+1)*32, (s+1) & 1);

        uint32_t sb = stg_b[s & 1];
        uint32_t sAh = sb, sAl = sb + G_ARR*2, sBh = sb + 2*G_ARR*2, sBl = sb + 3*G_ARR*2;
#pragma unroll
        for (int kk = 0; kk < 2; kk++){
            unsigned ah[2][4], al[2][4];
#pragma unroll
            for (int i=0;i<2;i++){
                unsigned off = (unsigned)(((arow + i*16)*40 + kk*16 + acol)*2);
                ldsm4(ah[i], sAh + off);
                ldsm4(al[i], sAl + off);
            }
#pragma unroll
            for (int jp=0;jp<4;jp++){
                unsigned bhf[2][2], blf[2][2];
#pragma unroll
                for (int jj=0;jj<2;jj++){
                    unsigned boff = (unsigned)(((wn*64 + (2*jp+jj)*8 + brow)*40 + kk*16 + bcol)*2);
                    ldsm2(bhf[jj], sBh + boff);
                    ldsm2(blf[jj], sBl + boff);
                }
                // term-major: 4 independent MMAs between dependent pairs
#pragma unroll
                for (int jj=0;jj<2;jj++)
#pragma unroll
                    for (int i=0;i<2;i++) mma_bf16(c[i][2*jp+jj], ah[i], bhf[jj]);
#pragma unroll
                for (int jj=0;jj<2;jj++)
#pragma unroll
                    for (int i=0;i<2;i++) mma_bf16(c[i][2*jp+jj], ah[i], blf[jj]);
#pragma unroll
                for (int jj=0;jj<2;jj++)
#pragma unroll
                    for (int i=0;i<2;i++) mma_bf16(c[i][2*jp+jj], al[i], bhf[jj]);
            }
        }
        __syncthreads();
    }

#pragma unroll
    for (int i=0;i<2;i++){
        int m0 = bm + wm*32 + i*16 + (L >> 2);
#pragma unroll
        for (int j=0;j<8;j++){
            int n = bn + wn*64 + j*8 + 2*(L & 3);
            float b0 = bias[n], b1 = bias[n+1];
            if (MODE == 1){
                float2 r0 = make_float2(c[i][j][0]+b0, c[i][j][1]+b1);
                float2 r1 = make_float2(c[i][j][2]+b0, c[i][j][3]+b1);
                *(float2*)&out[(size_t)m0*1024 + n] = r0;
                *(float2*)&out[(size_t)(m0+8)*1024 + n] = r1;
            } else {
                int third = n >> 10, rem = n & 1023;
                int h = rem >> 6, e = rem & 63;
                float sc = (third == 0) ? QSCALE : 1.0f;
                __nv_bfloat16* dh = (third==0) ? g_qh : (third==1) ? g_kh : g_vh;
                __nv_bfloat16* dl = (third==0) ? g_ql : (third==1) ? g_kl : g_vl;
#pragma unroll
                for (int rr = 0; rr < 2; rr++){
                    int m = m0 + rr*8;
                    int bb = m >> 9, tt = m & 511;
                    int idx = (third==0)
                        ? ((bb*Hq + h)*Tq + tt)*Eq + e
                        : ((bb*Hq + h)*Sq + Lq + tt)*Eq + e;
                    split_store(dh, dl, idx,
                                (c[i][j][2*rr]+b0)*sc, (c[i][j][2*rr+1]+b1)*sc);
                }
            }
        }
    }
}

// Fused launch: blocks 0..511 convert K/V cache, 512..767 convert Wproj^T,
// 768..1535 run the QKV GEMM tiles.
__global__ __launch_bounds__(256) void gemm0_fused(const float* __restrict__ bias,
                                                   const float* __restrict__ kc,
                                                   const float* __restrict__ vc,
                                                   const float* __restrict__ Wproj){
    extern __shared__ __align__(16) __nv_bfloat16 dsm[];
    const int bid = blockIdx.x;

    if (bid < 512){
#pragma unroll 4
        for (int it = 0; it < 32; it++){
            int base = ((bid + it*512)*256 + threadIdx.x)*4;
            int bh = base >> 17;
            int rem = base & (Lq*Eq - 1);
            int s = rem >> 6, e = rem & 63;
            int o = (bh*Sq + s)*Eq + e;
            float4 k4 = *(const float4*)&kc[base];
            float4 v4 = *(const float4*)&vc[base];
            split_store(g_kh, g_kl, o,   k4.x, k4.y);
            split_store(g_kh, g_kl, o+2, k4.z, k4.w);
            split_store(g_vh, g_vl, o,   v4.x, v4.y);
            split_store(g_vh, g_vl, o+2, v4.z, v4.w);
        }
        return;
    }
    if (bid < 768){
        float* tile = (float*)dsm;
        int id = bid - 512;
#pragma unroll
        for (int it = 0; it < 4; it++){
            int tl = id + it*256;                // 0..1023
            int n0 = (tl & 31)*32, k0 = (tl >> 5)*32;
            wT_tile_body(Wproj, 1024, g_wph, g_wpl, n0, k0, tile);
        }
        return;
    }
    int g = bid - 768;                            // 0..767
    gemm_body<0>((g / 24)*128, (g % 24)*128, bias, nullptr, dsm);
}

template<int MODE>
__global__ __launch_bounds__(256) void gemm_mma(const float* __restrict__ bias,
                                               float* __restrict__ out){
    extern __shared__ __align__(16) __nv_bfloat16 dsm[];
    gemm_body<MODE>(blockIdx.y*128, blockIdx.x*128, bias, out, dsm);
}

// ---------------- flash attention: 4 warps x 32 query rows -----------------
// Same structure as round-13, with term-major j-pair MMA interleave in both
// the S=QK^T and PV loops (dependent-MMA distance 1 -> 4).
#define A_ARR  (64*72)
#define A_STG  (4*A_ARR)
#define A_QOFF (2*128*72)
#define ATTN_SMEM ((A_QOFF + 2*A_STG)*2)    // 110592 B

__global__ __launch_bounds__(128, 2) void attn_mma(){
    extern __shared__ __align__(16) __nv_bfloat16 sm[];
    __nv_bfloat16* Qh = sm;
    __nv_bfloat16* Ql = sm + 128*72;

    const int bx = blockIdx.x;
    const int qt = 3 - (bx >> 7);          // longest-first
    const int bh = bx & 127;
    const int t = threadIdx.x, L = t & 31, w = t >> 5;   // w: 0..3

    unsigned sQh = (unsigned)__cvta_generic_to_shared(Qh);
    unsigned sQl = (unsigned)__cvta_generic_to_shared(Ql);
    unsigned sStg[2];
    sStg[0] = (unsigned)__cvta_generic_to_shared(sm + A_QOFF);
    sStg[1] = sStg[0] + A_STG*2;

    // load Q tile (128 rows, one row per thread)
    {
        int r = t;
        size_t gq = ((size_t)bh*Tq + qt*128 + r)*Eq;
#pragma unroll
        for (int i = 0; i < 8; i++){
            *(uint4*)&Qh[r*72 + i*8] = *(const uint4*)&g_qh[gq + i*8];
            *(uint4*)&Ql[r*72 + i*8] = *(const uint4*)&g_ql[gq + i*8];
        }
    }

    float o[2][8][4];
#pragma unroll
    for (int i2=0;i2<2;i2++)
#pragma unroll
        for (int j=0;j<8;j++)
#pragma unroll
            for (int q=0;q<4;q++) o[i2][j][q] = 0.f;
    float m_[2][2], l_[2][2];
#pragma unroll
    for (int i2=0;i2<2;i2++){ m_[i2][0]=m_[i2][1]=-1e30f; l_[i2][0]=l_[i2][1]=0.f; }

    const int KT = 34 + 2*qt;
    int lim[2][2];
#pragma unroll
    for (int i2=0;i2<2;i2++){
        int row0 = qt*128 + w*32 + i2*16 + (L >> 2);
        lim[i2][0] = Lq + row0; lim[i2][1] = Lq + row0 + 8;
    }

    const int ldr = t >> 1, ldc = t & 1;     // 64 rows, 2 threads/row
    const size_t kvbase = (size_t)bh*Sq*Eq;

    auto load_tile = [&](int kt, int stg){
        uint32_t sb = sStg[stg];
        size_t gi = kvbase + (size_t)(kt*64 + ldr)*Eq;
#pragma unroll
        for (int hh = 0; hh < 4; hh++){
            int cc = ldc*4 + hh;
            uint32_t d = sb + (uint32_t)((ldr*72 + cc*8)*2);
            cp16(d,               &g_kh[gi + cc*8]);
            cp16(d + A_ARR*2,     &g_kl[gi + cc*8]);
            cp16(d + 2*A_ARR*2,   &g_vh[gi + cc*8]);
            cp16(d + 3*A_ARR*2,   &g_vl[gi + cc*8]);
        }
        CP_COMMIT();
    };

    load_tile(0, 0);

    for (int kt = 0; kt < KT; kt++){
        CP_WAIT0();
        __syncthreads();
        if (kt + 1 < KT) load_tile(kt+1, (kt+1) & 1);

        uint32_t sb = sStg[kt & 1];
        uint32_t sKh = sb, sKl = sb + A_ARR*2, sVh = sb + 2*A_ARR*2, sVl = sb + 3*A_ARR*2;

        // ---- S = Q K^T (log2 domain) ----
        float s[2][8][4];
#pragma unroll
        for (int i2=0;i2<2;i2++)
#pragma unroll
            for (int j=0;j<8;j++)
#pragma unroll
                for (int q=0;q<4;q++) s[i2][j][q] = 0.f;

#pragma unroll
        for (int kk = 0; kk < 4; kk++){
            unsigned qa_h[2][4], qa_l[2][4];
#pragma unroll
            for (int i2=0;i2<2;i2++){
                unsigned qoff = (unsigned)(((w*32 + i2*16 + (L&15))*72 + kk*16 + (L>>4)*8)*2);
                ldsm4(qa_h[i2], sQh + qoff);
                ldsm4(qa_l[i2], sQl + qoff);
            }
#pragma unroll
            for (int jp=0;jp<4;jp++){
                unsigned kb_h[2][2], kb_l[2][2];
#pragma unroll
                for (int jj=0;jj<2;jj++){
                    unsigned koff = (unsigned)((((2*jp+jj)*8 + (L&7))*72 + kk*16 + ((L>>3)&1)*8)*2);
                    ldsm2(kb_h[jj], sKh + koff);
                    ldsm2(kb_l[jj], sKl + koff);
                }
#pragma unroll
                for (int jj=0;jj<2;jj++)
#pragma unroll
                    for (int i2=0;i2<2;i2++) mma_bf16(s[i2][2*jp+jj], qa_h[i2], kb_h[jj]);
#pragma unroll
                for (int jj=0;jj<2;jj++)
#pragma unroll
                    for (int i2=0;i2<2;i2++) mma_bf16(s[i2][2*jp+jj], qa_h[i2], kb_l[jj]);
#pragma unroll
                for (int jj=0;jj<2;jj++)
#pragma unroll
                    for (int i2=0;i2<2;i2++) mma_bf16(s[i2][2*jp+jj], qa_l[i2], kb_h[jj]);
            }
        }

        // ---- causal mask (diagonal band spans last 2 tiles) ----
        if (kt >= KT-2){
#pragma unroll
            for (int i2=0;i2<2;i2++)
#pragma unroll
                for (int j=0;j<8;j++){
                    int col = kt*64 + j*8 + 2*(L & 3);
                    if (col   > lim[i2][0]) s[i2][j][0] = -1e30f;
                    if (col+1 > lim[i2][0]) s[i2][j][1] = -1e30f;
                    if (col   > lim[i2][1]) s[i2][j][2] = -1e30f;
                    if (col+1 > lim[i2][1]) s[i2][j][3] = -1e30f;
                }
        }

        // ---- online softmax (exp2 domain, quad shuffles) ----
#pragma unroll
        for (int i2=0;i2<2;i2++){
            float mt0 = -1e30f, mt1 = -1e30f;
#pragma unroll
            for (int j=0;j<8;j++){
                mt0 = fmaxf(mt0, fmaxf(s[i2][j][0], s[i2][j][1]));
                mt1 = fmaxf(mt1, fmaxf(s[i2][j][2], s[i2][j][3]));
            }
            mt0 = fmaxf(mt0, __shfl_xor_sync(0xffffffffu, mt0, 1));
            mt0 = fmaxf(mt0, __shfl_xor_sync(0xffffffffu, mt0, 2));
            mt1 = fmaxf(mt1, __shfl_xor_sync(0xffffffffu, mt1, 1));
            mt1 = fmaxf(mt1, __shfl_xor_sync(0xffffffffu, mt1, 2));

            float nm0 = fmaxf(m_[i2][0], mt0), nm1 = fmaxf(m_[i2][1], mt1);
            float corr0 = ex2(m_[i2][0] - nm0), corr1 = ex2(m_[i2][1] - nm1);
            m_[i2][0] = nm0; m_[i2][1] = nm1;
            l_[i2][0] *= corr0; l_[i2][1] *= corr1;
#pragma unroll
            for (int j=0;j<8;j++){
                o[i2][j][0] *= corr0; o[i2][j][1] *= corr0;
                o[i2][j][2] *= corr1; o[i2][j][3] *= corr1;
            }
            float rs0 = 0.f, rs1 = 0.f;
#pragma unroll
            for (int j=0;j<8;j++){
                s[i2][j][0] = ex2(s[i2][j][0] - nm0); rs0 += s[i2][j][0];
                s[i2][j][1] = ex2(s[i2][j][1] - nm0); rs0 += s[i2][j][1];
                s[i2][j][2] = ex2(s[i2][j][2] - nm1); rs1 += s[i2][j][2];
                s[i2][j][3] = ex2(s[i2][j][3] - nm1); rs1 += s[i2][j][3];
            }
            rs0 += __shfl_xor_sync(0xffffffffu, rs0, 1);
            rs0 += __shfl_xor_sync(0xffffffffu, rs0, 2);
            rs1 += __shfl_xor_sync(0xffffffffu, rs1, 1);
            rs1 += __shfl_xor_sync(0xffffffffu, rs1, 2);
            l_[i2][0] += rs0; l_[i2][1] += rs1;
        }

        // ---- O += P V (term-major over j-pairs) ----
#pragma unroll
        for (int kk2 = 0; kk2 < 4; kk2++){
            unsigned pa_h[2][4], pa_l[2][4];
#pragma unroll
            for (int i2=0;i2<2;i2++){
                split_pack(s[i2][2*kk2][0],   s[i2][2*kk2][1],   pa_h[i2][0], pa_l[i2][0]);
                split_pack(s[i2][2*kk2][2],   s[i2][2*kk2][3],   pa_h[i2][1], pa_l[i2][1]);
                split_pack(s[i2][2*kk2+1][0], s[i2][2*kk2+1][1], pa_h[i2][2], pa_l[i2][2]);
                split_pack(s[i2][2*kk2+1][2], s[i2][2*kk2+1][3], pa_h[i2][3], pa_l[i2][3]);
            }
#pragma unroll
            for (int jp=0;jp<4;jp++){
                unsigned vb_h[2][2], vb_l[2][2];
#pragma unroll
                for (int jj=0;jj<2;jj++){
                    unsigned voff = (unsigned)(((kk2*16 + (L&15))*72 + (2*jp+jj)*8)*2);
                    ldsm2t(vb_h[jj], sVh + voff);
                    ldsm2t(vb_l[jj], sVl + voff);
                }
#pragma unroll
                for (int jj=0;jj<2;jj++)
#pragma unroll
                    for (int i2=0;i2<2;i2++) mma_bf16(o[i2][2*jp+jj], pa_h[i2], vb_h[jj]);
#pragma unroll
                for (int jj=0;jj<2;jj++)
#pragma unroll
                    for (int i2=0;i2<2;i2++) mma_bf16(o[i2][2*jp+jj], pa_h[i2], vb_l[jj]);
#pragma unroll
                for (int jj=0;jj<2;jj++)
#pragma unroll
                    for (int i2=0;i2<2;i2++) mma_bf16(o[i2][2*jp+jj], pa_l[i2], vb_h[jj]);
            }
        }
        __syncthreads();
    }

    // ---- finalize -> split y (b, t, h*64+e) ----
    int b_ = bh >> 4, h = bh & 15;
#pragma unroll
    for (int i2=0;i2<2;i2++){
        float inv0 = 1.0f / l_[i2][0], inv1 = 1.0f / l_[i2][1];
        int tok0 = qt*128 + w*32 + i2*16 + (L >> 2);
#pragma unroll
        for (int j=0;j<8;j++){
            int cc = h*Eq + j*8 + 2*(L & 3);
            int i0 = (b_*Tq + tok0)*Cq + cc;
            int i1 = (b_*Tq + tok0 + 8)*Cq + cc;
            split_store(g_yh, g_yl, i0, o[i2][j][0]*inv0, o[i2][j][1]*inv0);
            split_store(g_yh, g_yl, i1, o[i2][j][2]*inv1, o[i2][j][3]*inv1);
        }
    }
}

// ---------------------------------------------------------------------------
extern "C" void kernel_launch(void* const* d_in, const int* in_sizes, int n_in,
                              void* d_out, int out_size)
{
    const float* x     = (const float*)d_in[0];
    const float* kc    = (const float*)d_in[1];
    const float* vc    = (const float*)d_in[2];
    const float* Wqkv  = (const float*)d_in[3];
    const float* bqkv  = (const float*)d_in[4];
    const float* Wproj = (const float*)d_in[5];
    const float* bproj = (const float*)d_in[6];
    float* out = (float*)d_out;

    cudaFuncSetAttribute(attn_mma,
                         cudaFuncAttributeMaxDynamicSharedMemorySize, ATTN_SMEM);
    cudaFuncSetAttribute(gemm0_fused,
                         cudaFuncAttributeMaxDynamicSharedMemorySize, GEMM_SMEM);
    cudaFuncSetAttribute(gemm_mma<1>,
                         cudaFuncAttributeMaxDynamicSharedMemorySize, GEMM_SMEM);

    // 1) x + Wqkv^T conversions (predecessors of the QKV GEMM)
    cvt_pre<<<7168, 256>>>(x, Wqkv);

    // 2) QKV GEMM fused with K/V-cache + Wproj^T conversions
    gemm0_fused<<<1536, 256, GEMM_SMEM>>>(bqkv, kc, vc, Wproj);

    // 3) attention -> split y (4-warp blocks, longest first)
    attn_mma<<<512, 128, ATTN_SMEM>>>();

    // 4) output projection -> d_out (f32)
    gemm_mma<1><<<dim3(8, 32), 256, GEMM_SMEM>>>(bproj, out);
}

// round 15
// speedup vs baseline: 1.5355x; 1.5355x over previous
#include <cuda_runtime.h>
#include <cuda_fp16.h>
#include <cstdint>

#define Bq 8
#define Tq 512
#define Cq 1024
#define Hq 16
#define Eq 64
#define Lq 2048
#define Sq 2560   // L + T

// ---------------- fp16 scratch (device globals) ----------------
// A-side operands keep hi+lo (exact to 2^-23); B-side operands hi only.
__device__ __align__(16) __half g_xh[4096*1024], g_xl[4096*1024];
__device__ __align__(16) __half g_wqh[3072*1024];          // Wqkv^T (n,k) hi only
__device__ __align__(16) __half g_wph[1024*1024];          // Wproj^T hi only
__device__ __align__(16) __half g_qh[Bq*Hq*Tq*Eq], g_ql[Bq*Hq*Tq*Eq];
__device__ __align__(16) __half g_kh[Bq*Hq*Sq*Eq];         // K hi only (B-side)
__device__ __align__(16) __half g_vh[Bq*Hq*Sq*Eq];         // V hi only (B-side)
__device__ __align__(16) __half g_yh[4096*1024], g_yl[4096*1024];

// ---------------- PTX helpers ----------------
__device__ __forceinline__ void mma_f16(float* c, const unsigned* a, const unsigned* b){
    asm volatile(
        "mma.sync.aligned.m16n8k16.row.col.f32.f16.f16.f32 "
        "{%0,%1,%2,%3}, {%4,%5,%6,%7}, {%8,%9}, {%0,%1,%2,%3};\n"
        : "+f"(c[0]), "+f"(c[1]), "+f"(c[2]), "+f"(c[3])
        : "r"(a[0]), "r"(a[1]), "r"(a[2]), "r"(a[3]), "r"(b[0]), "r"(b[1]));
}
__device__ __forceinline__ void ldsm4(unsigned* r, unsigned addr){
    asm volatile("ldmatrix.sync.aligned.m8n8.x4.shared.b16 {%0,%1,%2,%3}, [%4];\n"
                 : "=r"(r[0]), "=r"(r[1]), "=r"(r[2]), "=r"(r[3]) : "r"(addr));
}
__device__ __forceinline__ void ldsm2(unsigned* r, unsigned addr){
    asm volatile("ldmatrix.sync.aligned.m8n8.x2.shared.b16 {%0,%1}, [%2];\n"
                 : "=r"(r[0]), "=r"(r[1]) : "r"(addr));
}
__device__ __forceinline__ void ldsm2t(unsigned* r, unsigned addr){
    asm volatile("ldmatrix.sync.aligned.m8n8.x2.trans.shared.b16 {%0,%1}, [%2];\n"
                 : "=r"(r[0]), "=r"(r[1]) : "r"(addr));
}
__device__ __forceinline__ void cp16(uint32_t dst, const void* src){
    asm volatile("cp.async.cg.shared.global [%0], [%1], 16;" :: "r"(dst), "l"(src) : "memory");
}
#define CP_COMMIT() asm volatile("cp.async.commit_group;" ::: "memory")
#define CP_WAIT0()  asm volatile("cp.async.wait_group 0;" ::: "memory")

__device__ __forceinline__ float ex2(float x){
    float y; asm("ex2.approx.ftz.f32 %0, %1;" : "=f"(y) : "f"(x)); return y;
}

// fp16 packers
__device__ __forceinline__ unsigned pack_h2(float x, float y){
    __half2 h = __floats2half2_rn(x, y);
    return *reinterpret_cast<unsigned*>(&h);
}
__device__ __forceinline__ void split_pack(float x, float y, unsigned& hi, unsigned& lo){
    __half hx = __float2half_rn(x), hy = __float2half_rn(y);
    __half lx = __float2half_rn(x - __half2float(hx));
    __half ly = __float2half_rn(y - __half2float(hy));
    __half2 H; H.x = hx; H.y = hy;
    __half2 Lo; Lo.x = lx; Lo.y = ly;
    hi = *reinterpret_cast<unsigned*>(&H);
    lo = *reinterpret_cast<unsigned*>(&Lo);
}
__device__ __forceinline__ void split_store(__half* dh, __half* dl,
                                            int idx, float x, float y){
    unsigned hi, lo; split_pack(x, y, hi, lo);
    *reinterpret_cast<unsigned*>(&dh[idx]) = hi;
    *reinterpret_cast<unsigned*>(&dl[idx]) = lo;
}

// ---------------- conversion bodies ----------------
// Weights: hi only (B-side operand)
__device__ __forceinline__ void wT_tile_body(const float* __restrict__ W, int N,
                                             __half* oh, int n0, int k0,
                                             float* tile /*32x33*/){
    int tx = threadIdx.x & 31, ty = threadIdx.x >> 5;
#pragma unroll
    for (int i = 0; i < 4; i++)
        tile[(ty + 8*i)*33 + tx] = W[(size_t)(k0 + ty + 8*i)*N + n0 + tx];
    __syncthreads();
#pragma unroll
    for (int i = 0; i < 4; i++){
        int n = n0 + ty + 8*i, k = k0 + tx;
        oh[(size_t)n*1024 + k] = __float2half_rn(tile[tx*33 + ty + 8*i]);
    }
    __syncthreads();
}

// Pre-kernel: x split + Wqkv^T hi (all predecessors of the QKV GEMM)
__global__ __launch_bounds__(256) void cvt_pre(const float* __restrict__ x,
                                               const float* __restrict__ Wqkv){
    __shared__ float tile[32*33];
    int bid = blockIdx.x;
    if (bid < 4096){
        int base = (bid*256 + threadIdx.x)*4;
        float4 v = *(const float4*)&x[base];
        split_store(g_xh, g_xl, base,   v.x, v.y);
        split_store(g_xh, g_xl, base+2, v.z, v.w);
    } else {
        int id = bid - 4096;                    // 0..3071
        int n0 = (id % 96)*32, k0 = (id / 96)*32;
        wT_tile_body(Wqkv, 3072, g_wqh, n0, k0, tile);
    }
}

// ---------------- GEMM sizes ----------------
#define G_ARR  (128*40)
#define G_STG  (3*G_ARR)                    // Ah, Al, Bh
#define GEMM_SMEM (2*G_STG*2)               // 61440 B

// log2(e)/8 : folds softmax base-2 conversion into the q scale
#define QSCALE 0.1803368801111204f

// Shared GEMM mainloop + epilogue (MODE 0 = qkv scatter, 1 = f32 out)
// C = (Ah + Al) @ Bh : 2 MMAs per (i,j) fragment.
template<int MODE>
__device__ __forceinline__ void gemm_body(int bm, int bn,
                                          const float* __restrict__ bias,
                                          float* __restrict__ out,
                                          __half* dsm){
    const __half* Ah = MODE ? g_yh : g_xh;
    const __half* Al = MODE ? g_yl : g_xl;
    const __half* Bh = MODE ? g_wph : g_wqh;

    const int t = threadIdx.x, L = t & 31, warp = t >> 5;
    const int wm = warp & 3, wn = warp >> 2;

    float c[2][8][4];
#pragma unroll
    for (int i=0;i<2;i++)
#pragma unroll
        for (int j=0;j<8;j++)
#pragma unroll
            for (int q=0;q<4;q++) c[i][j][q] = 0.f;

    const int lr = t >> 2, lc = t & 3;
    uint32_t sbase = (uint32_t)__cvta_generic_to_shared(dsm);
    uint32_t stg_b[2] = { sbase, sbase + G_STG*2 };

    const int arow = wm*32 + (L & 15);
    const int acol = (L >> 4)*8;
    const int brow = L & 7;
    const int bcol = ((L >> 3) & 1)*8;

    auto load_slab = [&](int k0, int stg){
        uint32_t sb = stg_b[stg];
#pragma unroll
        for (int hh = 0; hh < 2; hh++){
            int r = lr + hh*64;
            uint32_t d = sb + (uint32_t)((r*40 + lc*8)*2);
            size_t ga = (size_t)(bm + r)*1024 + k0 + lc*8;
            size_t gb = (size_t)(bn + r)*1024 + k0 + lc*8;
            cp16(d,                &Ah[ga]);
            cp16(d + G_ARR*2,      &Al[ga]);
            cp16(d + 2*G_ARR*2,    &Bh[gb]);
        }
        CP_COMMIT();
    };

    load_slab(0, 0);

    for (int s = 0; s < 32; s++){
        CP_WAIT0();
        __syncthreads();
        if (s + 1 < 32) load_slab((s+1)*32, (s+1) & 1);

        uint32_t sb = stg_b[s & 1];
        uint32_t sAh = sb, sAl = sb + G_ARR*2, sBh = sb + 2*G_ARR*2;
#pragma unroll
        for (int kk = 0; kk < 2; kk++){
            unsigned ah[2][4], al[2][4];
#pragma unroll
            for (int i=0;i<2;i++){
                unsigned off = (unsigned)(((arow + i*16)*40 + kk*16 + acol)*2);
                ldsm4(ah[i], sAh + off);
                ldsm4(al[i], sAl + off);
            }
#pragma unroll
            for (int j=0;j<8;j++){
                unsigned boff = (unsigned)(((wn*64 + j*8 + brow)*40 + kk*16 + bcol)*2);
                unsigned bhf[2];
                ldsm2(bhf, sBh + boff);
#pragma unroll
                for (int i=0;i<2;i++){
                    mma_f16(c[i][j], ah[i], bhf);
                    mma_f16(c[i][j], al[i], bhf);
                }
            }
        }
        __syncthreads();
    }

#pragma unroll
    for (int i=0;i<2;i++){
        int m0 = bm + wm*32 + i*16 + (L >> 2);
#pragma unroll
        for (int j=0;j<8;j++){
            int n = bn + wn*64 + j*8 + 2*(L & 3);
            float b0 = bias[n], b1 = bias[n+1];
            if (MODE == 1){
                float2 r0 = make_float2(c[i][j][0]+b0, c[i][j][1]+b1);
                float2 r1 = make_float2(c[i][j][2]+b0, c[i][j][3]+b1);
                *(float2*)&out[(size_t)m0*1024 + n] = r0;
                *(float2*)&out[(size_t)(m0+8)*1024 + n] = r1;
            } else {
                int third = n >> 10, rem = n & 1023;
                int h = rem >> 6, e = rem & 63;
#pragma unroll
                for (int rr = 0; rr < 2; rr++){
                    int m = m0 + rr*8;
                    int bb = m >> 9, tt = m & 511;
                    float vx = c[i][j][2*rr] + b0, vy = c[i][j][2*rr+1] + b1;
                    if (third == 0){
                        int idx = ((bb*Hq + h)*Tq + tt)*Eq + e;
                        split_store(g_qh, g_ql, idx, vx*QSCALE, vy*QSCALE);
                    } else {
                        int idx = ((bb*Hq + h)*Sq + Lq + tt)*Eq + e;
                        __half* dh = (third==1) ? g_kh : g_vh;
                        *reinterpret_cast<unsigned*>(&dh[idx]) = pack_h2(vx, vy);
                    }
                }
            }
        }
    }
}

// Fused launch: blocks 0..511 convert K/V cache (hi only), 512..767 convert
// Wproj^T (hi only), 768..1535 run the QKV GEMM tiles.
__global__ __launch_bounds__(256) void gemm0_fused(const float* __restrict__ bias,
                                                   const float* __restrict__ kc,
                                                   const float* __restrict__ vc,
                                                   const float* __restrict__ Wproj){
    extern __shared__ __align__(16) __half dsm[];
    const int bid = blockIdx.x;

    if (bid < 512){
#pragma unroll 4
        for (int it = 0; it < 32; it++){
            int base = ((bid + it*512)*256 + threadIdx.x)*4;
            int bh = base >> 17;
            int rem = base & (Lq*Eq - 1);
            int s = rem >> 6, e = rem & 63;
            int o = (bh*Sq + s)*Eq + e;
            float4 k4 = *(const float4*)&kc[base];
            float4 v4 = *(const float4*)&vc[base];
            *reinterpret_cast<unsigned*>(&g_kh[o])   = pack_h2(k4.x, k4.y);
            *reinterpret_cast<unsigned*>(&g_kh[o+2]) = pack_h2(k4.z, k4.w);
            *reinterpret_cast<unsigned*>(&g_vh[o])   = pack_h2(v4.x, v4.y);
            *reinterpret_cast<unsigned*>(&g_vh[o+2]) = pack_h2(v4.z, v4.w);
        }
        return;
    }
    if (bid < 768){
        float* tile = (float*)dsm;
        int id = bid - 512;
#pragma unroll
        for (int it = 0; it < 4; it++){
            int tl = id + it*256;                // 0..1023
            int n0 = (tl & 31)*32, k0 = (tl >> 5)*32;
            wT_tile_body(Wproj, 1024, g_wph, n0, k0, tile);
        }
        return;
    }
    int g = bid - 768;                            // 0..767
    gemm_body<0>((g / 24)*128, (g % 24)*128, bias, nullptr, dsm);
}

template<int MODE>
__global__ __launch_bounds__(256) void gemm_mma(const float* __restrict__ bias,
                                               float* __restrict__ out){
    extern __shared__ __align__(16) __half dsm[];
    gemm_body<MODE>(blockIdx.y*128, blockIdx.x*128, bias, out, dsm);
}

// ---------------- flash attention: 4 warps x 32 query rows, fp16 -----------
// S = (Qh+Ql)·Kh (2 MMAs), O += (Ph+Pl)·Vh (2 MMAs). K/V hi only in smem.
#define A_ARR  (64*72)
#define A_STG  (2*A_ARR)                    // Kh, Vh
#define A_QOFF (2*128*72)
#define ATTN_SMEM ((A_QOFF + 2*A_STG)*2)    // 73728 B

__global__ __launch_bounds__(128, 2) void attn_mma(){
    extern __shared__ __align__(16) __half sm[];
    __half* Qh = sm;
    __half* Ql = sm + 128*72;

    const int bx = blockIdx.x;
    const int qt = 3 - (bx >> 7);          // longest-first
    const int bh = bx & 127;
    const int t = threadIdx.x, L = t & 31, w = t >> 5;   // w: 0..3

    unsigned sQh = (unsigned)__cvta_generic_to_shared(Qh);
    unsigned sQl = (unsigned)__cvta_generic_to_shared(Ql);
    unsigned sStg[2];
    sStg[0] = (unsigned)__cvta_generic_to_shared(sm + A_QOFF);
    sStg[1] = sStg[0] + A_STG*2;

    // load Q tile (128 rows, one row per thread)
    {
        int r = t;
        size_t gq = ((size_t)bh*Tq + qt*128 + r)*Eq;
#pragma unroll
        for (int i = 0; i < 8; i++){
            *(uint4*)&Qh[r*72 + i*8] = *(const uint4*)&g_qh[gq + i*8];
            *(uint4*)&Ql[r*72 + i*8] = *(const uint4*)&g_ql[gq + i*8];
        }
    }

    float o[2][8][4];
#pragma unroll
    for (int i2=0;i2<2;i2++)
#pragma unroll
        for (int j=0;j<8;j++)
#pragma unroll
            for (int q=0;q<4;q++) o[i2][j][q] = 0.f;
    float m_[2][2], l_[2][2];
#pragma unroll
    for (int i2=0;i2<2;i2++){ m_[i2][0]=m_[i2][1]=-1e30f; l_[i2][0]=l_[i2][1]=0.f; }

    const int KT = 34 + 2*qt;
    int lim[2][2];
#pragma unroll
    for (int i2=0;i2<2;i2++){
        int row0 = qt*128 + w*32 + i2*16 + (L >> 2);
        lim[i2][0] = Lq + row0; lim[i2][1] = Lq + row0 + 8;
    }

    const int ldr = t >> 1, ldc = t & 1;     // 64 rows, 2 threads/row
    const size_t kvbase = (size_t)bh*Sq*Eq;

    auto load_tile = [&](int kt, int stg){
        uint32_t sb = sStg[stg];
        size_t gi = kvbase + (size_t)(kt*64 + ldr)*Eq;
#pragma unroll
        for (int hh = 0; hh < 4; hh++){
            int cc = ldc*4 + hh;
            uint32_t d = sb + (uint32_t)((ldr*72 + cc*8)*2);
            cp16(d,           &g_kh[gi + cc*8]);
            cp16(d + A_ARR*2, &g_vh[gi + cc*8]);
        }
        CP_COMMIT();
    };

    load_tile(0, 0);

    for (int kt = 0; kt < KT; kt++){
        CP_WAIT0();
        __syncthreads();
        if (kt + 1 < KT) load_tile(kt+1, (kt+1) & 1);

        uint32_t sb = sStg[kt & 1];
        uint32_t sKh = sb, sVh = sb + A_ARR*2;

        // ---- S = Q K^T (log2 domain) ----
        float s[2][8][4];
#pragma unroll
        for (int i2=0;i2<2;i2++)
#pragma unroll
            for (int j=0;j<8;j++)
#pragma unroll
                for (int q=0;q<4;q++) s[i2][j][q] = 0.f;

#pragma unroll
        for (int kk = 0; kk < 4; kk++){
            unsigned qa_h[2][4], qa_l[2][4];
#pragma unroll
            for (int i2=0;i2<2;i2++){
                unsigned qoff = (unsigned)(((w*32 + i2*16 + (L&15))*72 + kk*16 + (L>>4)*8)*2);
                ldsm4(qa_h[i2], sQh + qoff);
                ldsm4(qa_l[i2], sQl + qoff);
            }
#pragma unroll
            for (int j=0;j<8;j++){
                unsigned koff = (unsigned)(((j*8 + (L&7))*72 + kk*16 + ((L>>3)&1)*8)*2);
                unsigned kb_h[2];
                ldsm2(kb_h, sKh + koff);
#pragma unroll
                for (int i2=0;i2<2;i2++){
                    mma_f16(s[i2][j], qa_h[i2], kb_h);
                    mma_f16(s[i2][j], qa_l[i2], kb_h);
                }
            }
        }

        // ---- causal mask (diagonal band spans last 2 tiles) ----
        if (kt >= KT-2){
#pragma unroll
            for (int i2=0;i2<2;i2++)
#pragma unroll
                for (int j=0;j<8;j++){
                    int col = kt*64 + j*8 + 2*(L & 3);
                    if (col   > lim[i2][0]) s[i2][j][0] = -1e30f;
                    if (col+1 > lim[i2][0]) s[i2][j][1] = -1e30f;
                    if (col   > lim[i2][1]) s[i2][j][2] = -1e30f;
                    if (col+1 > lim[i2][1]) s[i2][j][3] = -1e30f;
                }
        }

        // ---- online softmax (exp2 domain, quad shuffles) ----
#pragma unroll
        for (int i2=0;i2<2;i2++){
            float mt0 = -1e30f, mt1 = -1e30f;
#pragma unroll
            for (int j=0;j<8;j++){
                mt0 = fmaxf(mt0, fmaxf(s[i2][j][0], s[i2][j][1]));
                mt1 = fmaxf(mt1, fmaxf(s[i2][j][2], s[i2][j][3]));
            }
            mt0 = fmaxf(mt0, __shfl_xor_sync(0xffffffffu, mt0, 1));
            mt0 = fmaxf(mt0, __shfl_xor_sync(0xffffffffu, mt0, 2));
            mt1 = fmaxf(mt1, __shfl_xor_sync(0xffffffffu, mt1, 1));
            mt1 = fmaxf(mt1, __shfl_xor_sync(0xffffffffu, mt1, 2));

            float nm0 = fmaxf(m_[i2][0], mt0), nm1 = fmaxf(m_[i2][1], mt1);
            float corr0 = ex2(m_[i2][0] - nm0), corr1 = ex2(m_[i2][1] - nm1);
            m_[i2][0] = nm0; m_[i2][1] = nm1;
            l_[i2][0] *= corr0; l_[i2][1] *= corr1;
#pragma unroll
            for (int j=0;j<8;j++){
                o[i2][j][0] *= corr0; o[i2][j][1] *= corr0;
                o[i2][j][2] *= corr1; o[i2][j][3] *= corr1;
            }
            float rs0 = 0.f, rs1 = 0.f;
#pragma unroll
            for (int j=0;j<8;j++){
                s[i2][j][0] = ex2(s[i2][j][0] - nm0); rs0 += s[i2][j][0];
                s[i2][j][1] = ex2(s[i2][j][1] - nm0); rs0 += s[i2][j][1];
                s[i2][j][2] = ex2(s[i2][j][2] - nm1); rs1 += s[i2][j][2];
                s[i2][j][3] = ex2(s[i2][j][3] - nm1); rs1 += s[i2][j][3];
            }
            rs0 += __shfl_xor_sync(0xffffffffu, rs0, 1);
            rs0 += __shfl_xor_sync(0xffffffffu, rs0, 2);
            rs1 += __shfl_xor_sync(0xffffffffu, rs1, 1);
            rs1 += __shfl_xor_sync(0xffffffffu, rs1, 2);
            l_[i2][0] += rs0; l_[i2][1] += rs1;
        }

        // ---- O += P V ----
#pragma unroll
        for (int kk2 = 0; kk2 < 4; kk2++){
            unsigned pa_h[2][4], pa_l[2][4];
#pragma unroll
            for (int i2=0;i2<2;i2++){
                split_pack(s[i2][2*kk2][0],   s[i2][2*kk2][1],   pa_h[i2][0], pa_l[i2][0]);
                split_pack(s[i2][2*kk2][2],   s[i2][2*kk2][3],   pa_h[i2][1], pa_l[i2][1]);
                split_pack(s[i2][2*kk2+1][0], s[i2][2*kk2+1][1], pa_h[i2][2], pa_l[i2][2]);
                split_pack(s[i2][2*kk2+1][2], s[i2][2*kk2+1][3], pa_h[i2][3], pa_l[i2][3]);
            }
#pragma unroll
            for (int j=0;j<8;j++){
                unsigned voff = (unsigned)(((kk2*16 + (L&15))*72 + j*8)*2);
                unsigned vb_h[2];
                ldsm2t(vb_h, sVh + voff);
#pragma unroll
                for (int i2=0;i2<2;i2++){
                    mma_f16(o[i2][j], pa_h[i2], vb_h);
                    mma_f16(o[i2][j], pa_l[i2], vb_h);
                }
            }
        }
        __syncthreads();
    }

    // ---- finalize -> split y (b, t, h*64+e) ----
    int b_ = bh >> 4, h = bh & 15;
#pragma unroll
    for (int i2=0;i2<2;i2++){
        float inv0 = 1.0f / l_[i2][0], inv1 = 1.0f / l_[i2][1];
        int tok0 = qt*128 + w*32 + i2*16 + (L >> 2);
#pragma unroll
        for (int j=0;j<8;j++){
            int cc = h*Eq + j*8 + 2*(L & 3);
            int i0 = (b_*Tq + tok0)*Cq + cc;
            int i1 = (b_*Tq + tok0 + 8)*Cq + cc;
            split_store(g_yh, g_yl, i0, o[i2][j][0]*inv0, o[i2][j][1]*inv0);
            split_store(g_yh, g_yl, i1, o[i2][j][2]*inv1, o[i2][j][3]*inv1);
        }
    }
}

// ---------------------------------------------------------------------------
extern "C" void kernel_launch(void* const* d_in, const int* in_sizes, int n_in,
                              void* d_out, int out_size)
{
    const float* x     = (const float*)d_in[0];
    const float* kc    = (const float*)d_in[1];
    const float* vc    = (const float*)d_in[2];
    const float* Wqkv  = (const float*)d_in[3];
    const float* bqkv  = (const float*)d_in[4];
    const float* Wproj = (const float*)d_in[5];
    const float* bproj = (const float*)d_in[6];
    float* out = (float*)d_out;

    cudaFuncSetAttribute(attn_mma,
                         cudaFuncAttributeMaxDynamicSharedMemorySize, ATTN_SMEM);
    cudaFuncSetAttribute(gemm0_fused,
                         cudaFuncAttributeMaxDynamicSharedMemorySize, GEMM_SMEM);
    cudaFuncSetAttribute(gemm_mma<1>,
                         cudaFuncAttributeMaxDynamicSharedMemorySize, GEMM_SMEM);

    // 1) x split + Wqkv^T hi (predecessors of the QKV GEMM)
    cvt_pre<<<7168, 256>>>(x, Wqkv);

    // 2) QKV GEMM fused with K/V-cache + Wproj^T conversions
    gemm0_fused<<<1536, 256, GEMM_SMEM>>>(bqkv, kc, vc, Wproj);

    // 3) attention -> split y (4-warp blocks, longest first)
    attn_mma<<<512, 128, ATTN_SMEM>>>();

    // 4) output projection -> d_out (f32)
    gemm_mma<1><<<dim3(8, 32), 256, GEMM_SMEM>>>(bproj, out);
}